// round 12
// baseline (speedup 1.0000x reference)
#include <cuda_runtime.h>
#include <cuda_bf16.h>
#include <cstdint>
#include <math.h>

#define B_ 16384
#define N_ 256
#define M_ 64
#define L_ 10
#define NB (B_ * N_)

// Planes: 0 Ahy_r, 1 Ahy_i, 2+s zr[s], 4+s zi[s], 6+s vr[s], 8+s vi[s]
__device__ float g_scr[10u * (unsigned)NB];
__device__ float g_wts[4 * L_ * N_ * N_];   // f32 weights: [l][s][n][k], s: Wr,Ur,Wi,Ui
__device__ float g_stat[4 * N_];
__device__ int   g_bf16;

__device__ __forceinline__ float sigm(float x) { return 1.f / (1.f + __expf(-x)); }
__device__ __forceinline__ float* plane(int p) { return g_scr + (unsigned)p * (unsigned)NB; }
__device__ __forceinline__ float lda(const void* p, unsigned idx, int isbf) {
    if (isbf) return __bfloat162float(((const __nv_bfloat16*)p)[idx]);
    return ((const float*)p)[idx];
}
__device__ __forceinline__ uint32_t sptr(const void* p) {
    return (uint32_t)__cvta_generic_to_shared(p);
}
__device__ __forceinline__ void cpa16(uint32_t d, const void* s) {
    asm volatile("cp.async.cg.shared.global [%0], [%1], 16;" :: "r"(d), "l"(s));
}
__device__ __forceinline__ void mma8(float* c, const float* a, const float* b) {
    asm volatile(
        "mma.sync.aligned.m16n8k8.row.col.f32.tf32.tf32.f32 "
        "{%0,%1,%2,%3}, {%4,%5,%6,%7}, {%8,%9}, {%0,%1,%2,%3};\n"
        : "+f"(c[0]), "+f"(c[1]), "+f"(c[2]), "+f"(c[3])
        : "r"(__float_as_uint(a[0])), "r"(__float_as_uint(a[1])),
          "r"(__float_as_uint(a[2])), "r"(__float_as_uint(a[3])),
          "r"(__float_as_uint(b[0])), "r"(__float_as_uint(b[1])));
}

// ---------------- K_init: probe dtype + zero stats (1 block) ----------------
__global__ void k_init(const void* A) {
    __shared__ int sane;
    unsigned t = threadIdx.x;
    if (t == 0) sane = 0;
#pragma unroll
    for (int j = 0; j < 4; j++) g_stat[t + 256u * j] = 0.f;
    __syncthreads();
    const unsigned short* h = (const unsigned short*)A;
    int loc = 0;
#pragma unroll
    for (int j = 0; j < 8; j++) {
        unsigned short v = h[2 * (t * 8 + j)];
        unsigned e = (v >> 7) & 0xFF;
        if (v == 0 || (e >= 100 && e <= 140)) loc++;
    }
    atomicAdd(&sane, loc);
    __syncthreads();
    if (t == 0) g_bf16 = (sane > 1228) ? 1 : 0;
}

// ---------------- K_prep: weights -> f32 arena [l][s][n][k] ----------------
__global__ void k_prep(const void* w0, const void* w1, const void* w2, const void* w3) {
    const int isbf = g_bf16;
    unsigned idx = blockIdx.x * 256u + threadIdx.x;     // 0 .. 4*L*N*N-1
    unsigned s = (idx >> 16) & 3u;
    unsigned l = idx >> 18;
    unsigned nk = idx & 65535u;
    const void* ws = (s == 0) ? w0 : (s == 1) ? w1 : (s == 2) ? w2 : w3;
    g_wts[((l * 4u + s) << 16) + nk] = lda(ws, (l << 16) + nk, isbf);
}

// ---------------- K1: A^H y + BN partial stats ----------------
// grid B/4, 256 thr: ty=row(4), tx=col-group(64); float4 per thread (f32 path).
__global__ void k_ahy(const void* yrv, const void* yiv, const void* Arv, const void* Aiv) {
    __shared__ float syr[4][64], syi[4][64];
    const unsigned t = threadIdx.x, tx = t & 63u, ty = t >> 6;
    const unsigned b0 = blockIdx.x * 4u;
    const int isbf = g_bf16;
    {
        unsigned r = t >> 6, c = t & 63u;
        syr[r][c] = lda(yrv, (b0 + r) * 64u + c, isbf);
        syi[r][c] = lda(yiv, (b0 + r) * 64u + c, isbf);
    }
    __syncthreads();

    float4 ar = make_float4(0.f, 0.f, 0.f, 0.f);
    float4 ai = make_float4(0.f, 0.f, 0.f, 0.f);
    if (!isbf) {
        const float4* A4r = (const float4*)Arv;
        const float4* A4i = (const float4*)Aiv;
        size_t base = (size_t)(b0 + ty) * 4096u + tx;
#pragma unroll 8
        for (int m = 0; m < 64; m++) {
            float4 pr = A4r[base + (size_t)m * 64u];
            float4 pi = A4i[base + (size_t)m * 64u];
            float wr = syr[ty][m], wi = syi[ty][m];
            ar.x += pr.x * wr + pi.x * wi;  ai.x += pr.x * wi - pi.x * wr;
            ar.y += pr.y * wr + pi.y * wi;  ai.y += pr.y * wi - pi.y * wr;
            ar.z += pr.z * wr + pi.z * wi;  ai.z += pr.z * wi - pi.z * wr;
            ar.w += pr.w * wr + pi.w * wi;  ai.w += pr.w * wi - pi.w * wr;
        }
    } else {
        size_t base = (size_t)(b0 + ty) * 16384u + tx * 4u;
        const __nv_bfloat16* Abr = (const __nv_bfloat16*)Arv;
        const __nv_bfloat16* Abi = (const __nv_bfloat16*)Aiv;
#pragma unroll 4
        for (int m = 0; m < 64; m++) {
            float wr = syr[ty][m], wi = syi[ty][m];
            size_t o = base + (size_t)m * 256u;
            float p0r = __bfloat162float(Abr[o]),     p0i = __bfloat162float(Abi[o]);
            float p1r = __bfloat162float(Abr[o + 1]), p1i = __bfloat162float(Abi[o + 1]);
            float p2r = __bfloat162float(Abr[o + 2]), p2i = __bfloat162float(Abi[o + 2]);
            float p3r = __bfloat162float(Abr[o + 3]), p3i = __bfloat162float(Abi[o + 3]);
            ar.x += p0r * wr + p0i * wi;  ai.x += p0r * wi - p0i * wr;
            ar.y += p1r * wr + p1i * wi;  ai.y += p1r * wi - p1i * wr;
            ar.z += p2r * wr + p2i * wi;  ai.z += p2r * wi - p2i * wr;
            ar.w += p3r * wr + p3i * wi;  ai.w += p3r * wi - p3i * wr;
        }
    }
    unsigned o4 = (b0 + ty) * 64u + tx;
    ((float4*)plane(0))[o4] = ar;
    ((float4*)plane(1))[o4] = ai;

    unsigned n0 = tx * 4u;
    atomicAdd(&g_stat[n0],        ar.x); atomicAdd(&g_stat[256u + n0],        ar.x * ar.x);
    atomicAdd(&g_stat[n0 + 1],    ar.y); atomicAdd(&g_stat[256u + n0 + 1],    ar.y * ar.y);
    atomicAdd(&g_stat[n0 + 2],    ar.z); atomicAdd(&g_stat[256u + n0 + 2],    ar.z * ar.z);
    atomicAdd(&g_stat[n0 + 3],    ar.w); atomicAdd(&g_stat[256u + n0 + 3],    ar.w * ar.w);
    atomicAdd(&g_stat[512u + n0],     ai.x); atomicAdd(&g_stat[768u + n0],     ai.x * ai.x);
    atomicAdd(&g_stat[512u + n0 + 1], ai.y); atomicAdd(&g_stat[768u + n0 + 1], ai.y * ai.y);
    atomicAdd(&g_stat[512u + n0 + 2], ai.z); atomicAdd(&g_stat[768u + n0 + 2], ai.z * ai.z);
    atomicAdd(&g_stat[512u + n0 + 3], ai.w); atomicAdd(&g_stat[768u + n0 + 3], ai.w * ai.w);
}

// ---------------- K3: BN finalize (inline) + layer 0 ----------------
__global__ void k_layer0(const void* wdr, const void* wdi, const void* reta,
                         const void* br, const void* ubr,
                         const void* bi, const void* ubi) {
    const int isbf = g_bf16;
    unsigned idx = blockIdx.x * 256u + threadIdx.x;
    unsigned n = idx & (unsigned)(N_ - 1);
    const float invB = 1.f / (float)B_;
    float mr = g_stat[n] * invB;
    float istr = rsqrtf(g_stat[256u + n] * invB - mr * mr + 1e-5f);
    float mi = g_stat[512u + n] * invB;
    float isti = rsqrtf(g_stat[768u + n] * invB - mi * mi + 1e-5f);

    float* Ahr = plane(0); float* Ahi = plane(1);
    float eta = log1pf(expf(lda(reta, 0, isbf)));
    float arr = (Ahr[idx] - mr) * istr;
    float aii = (Ahi[idx] - mi) * isti;
    Ahr[idx] = arr;
    Ahi[idx] = aii;
    float dr = lda(wdr, n, isbf) + eta, di = lda(wdi, n, isbf);
    float inv = 1.f / (dr * dr + di * di);
    float xr = (arr * dr + aii * di) * inv;
    float xi = (aii * dr - arr * di) * inv;
    float gr = sigm(lda(br, n, isbf) + lda(ubr, n, isbf));
    float gi = sigm(lda(bi, n, isbf) + lda(ubi, n, isbf));
    float zr = gr * xr - gi * xi;
    float zi = gr * xi + gi * xr;
    plane(2)[idx] = zr;
    plane(4)[idx] = zi;
    plane(6)[idx] = xr - zr;
    plane(8)[idx] = xi - zi;
}

// ---------------- K4: fused layer — cp.async pipelined tf32 MMA ----------------
// grid (4,128), 256 thr; tile 128x64; 32 stages (4 operand pairs x 8 K-chunks).
__global__ __launch_bounds__(256, 2) void k_layer(
    const void* br, const void* ubr, const void* bi, const void* ubi,
    const void* wdr, const void* wdi, const void* reta,
    int loff, int si, int so, int last,
    const void* thrp, const void* alphap,
    float* __restrict__ out, long long outCap)
{
    extern __shared__ float sm[];
    float* sA0 = sm;                 // 128*36
    float* sA1 = sA0 + 128 * 36;
    float* sB0 = sA1 + 128 * 36;     // 64*36
    float* sB1 = sB0 + 64 * 36;
    __shared__ float sPar[4][64];

    const int isbf = g_bf16;
    const unsigned tid  = threadIdx.x;
    const unsigned lane = tid & 31u, warp = tid >> 5;
    const unsigned wrow = (warp >> 1) * 32u;
    const unsigned wcol = (warp & 1u) * 32u;
    const unsigned tg = lane >> 2, tc = lane & 3u;
    const unsigned rowBase = blockIdx.y * 128u;
    const unsigned colBase = blockIdx.x * 64u;
    const unsigned siu = (unsigned)(si & 1);

    float eta = log1pf(expf(lda(reta, (unsigned)loff, isbf)));
    if (tid < 64u) {
        unsigned bn = (unsigned)loff * 256u + colBase + tid;
        sPar[0][tid] = lda(wdr, bn, isbf) + eta;
        sPar[1][tid] = lda(wdi, bn, isbf);
        sPar[2][tid] = lda(br, bn, isbf) + lda(ubr, bn, isbf);
        sPar[3][tid] = lda(bi, bn, isbf) + lda(ubi, bn, isbf);
    }

    float acc[2][2][4][4];
#pragma unroll
    for (int a = 0; a < 2; a++)
#pragma unroll
        for (int b = 0; b < 2; b++)
#pragma unroll
            for (int c = 0; c < 4; c++)
#pragma unroll
                for (int d = 0; d < 4; d++) acc[a][b][c][d] = 0.f;

    // ---- stage prefetch: s = t>>3 (operand pair), kc = (t&7)*32 ----
#define PREFETCH(t_) do {                                                          \
        int s_ = (t_) >> 3;                                                        \
        unsigned kc_ = (unsigned)((t_) & 7) * 32u;                                 \
        const float* Ap_ = g_scr +                                                 \
            (unsigned)(2 + (s_ & 1) * 4 + (s_ >> 1) * 2 + (int)siu) * (unsigned)NB;\
        const float* Wp_ = g_wts + (((unsigned)loff * 4u + (unsigned)s_) << 16);   \
        float* dA_ = ((t_) & 1) ? sA1 : sA0;                                       \
        float* dB_ = ((t_) & 1) ? sB1 : sB0;                                       \
        _Pragma("unroll")                                                          \
        for (int i_ = 0; i_ < 4; i_++) {                                           \
            unsigned e_ = tid + i_ * 256u, r_ = e_ >> 3, c4_ = (e_ & 7u) * 4u;     \
            cpa16(sptr(dA_ + r_ * 36u + c4_), Ap_ + (rowBase + r_) * 256u + kc_ + c4_); \
        }                                                                          \
        _Pragma("unroll")                                                          \
        for (int i_ = 0; i_ < 2; i_++) {                                           \
            unsigned e_ = tid + i_ * 256u, r_ = e_ >> 3, c4_ = (e_ & 7u) * 4u;     \
            cpa16(sptr(dB_ + r_ * 36u + c4_), Wp_ + (colBase + r_) * 256u + kc_ + c4_); \
        }                                                                          \
        asm volatile("cp.async.commit_group;");                                    \
    } while (0)

    PREFETCH(0);
    for (int t = 0; t < 32; ++t) {
        if (t < 31) {
            PREFETCH(t + 1);
            asm volatile("cp.async.wait_group 1;");
        } else {
            asm volatile("cp.async.wait_group 0;");
        }
        __syncthreads();
        const float* bAp = (t & 1) ? sA1 : sA0;
        const float* bBp = (t & 1) ? sB1 : sB0;
        const int comp = t >> 4;
#pragma unroll
        for (unsigned kk = 0; kk < 32u; kk += 8u) {
            float af[2][4];
#pragma unroll
            for (int tm = 0; tm < 2; tm++) {
                unsigned r0 = wrow + tm * 16u + tg;
                af[tm][0] = bAp[r0 * 36u + kk + tc];
                af[tm][1] = bAp[(r0 + 8u) * 36u + kk + tc];
                af[tm][2] = bAp[r0 * 36u + kk + tc + 4u];
                af[tm][3] = bAp[(r0 + 8u) * 36u + kk + tc + 4u];
            }
            float bfv[4][2];
#pragma unroll
            for (int tn = 0; tn < 4; tn++) {
                unsigned n0 = wcol + tn * 8u + tg;
                bfv[tn][0] = bBp[n0 * 36u + kk + tc];
                bfv[tn][1] = bBp[n0 * 36u + kk + tc + 4u];
            }
#pragma unroll
            for (int tm = 0; tm < 2; tm++)
#pragma unroll
                for (int tn = 0; tn < 4; tn++)
                    mma8(acc[comp][tm][tn], af[tm], bfv[tn]);
        }
        __syncthreads();
    }
#undef PREFETCH

    // ----- epilogue (float2) -----
    float thv = 0.f, alv = 0.f;
    if (last) { thv = lda(thrp, 0, isbf); alv = lda(alphap, 0, isbf); }

    const float* __restrict__ zri = plane(2 + (int)siu);
    const float* __restrict__ zii = plane(4 + (int)siu);
    const float* __restrict__ vri = plane(6 + (int)siu);
    const float* __restrict__ vii = plane(8 + (int)siu);
    const float* __restrict__ Ahr = plane(0);
    const float* __restrict__ Ahi = plane(1);
    float* __restrict__ zro = plane(2 + (so & 1));
    float* __restrict__ zio = plane(4 + (so & 1));
    float* __restrict__ vro = plane(6 + (so & 1));
    float* __restrict__ vio = plane(8 + (so & 1));

#pragma unroll
    for (int tm = 0; tm < 2; tm++)
#pragma unroll
    for (int j = 0; j < 2; j++)
#pragma unroll
    for (int tn = 0; tn < 4; tn++) {
        unsigned b = rowBase + wrow + tm * 16u + j * 8u + tg;
        unsigned ln = wcol + tn * 8u + 2u * tc;
        unsigned off = b * (unsigned)N_ + colBase + ln;

        float2 z2 = *(const float2*)(zri + off);
        float2 i2 = *(const float2*)(zii + off);
        float2 v2 = *(const float2*)(vri + off);
        float2 w2 = *(const float2*)(vii + off);
        float2 h2 = *(const float2*)(Ahr + off);
        float2 g2 = *(const float2*)(Ahi + off);

        float zra[2] = {z2.x, z2.y}, zia[2] = {i2.x, i2.y};
        float vra[2] = {v2.x, v2.y}, via[2] = {w2.x, w2.y};
        float hra[2] = {h2.x, h2.y}, hia[2] = {g2.x, g2.y};

        float znv[2], ziv[2], vnv[2], viv[2], ov[2];
#pragma unroll
        for (int c = 0; c < 2; c++) {
            unsigned nl = ln + c;
            float dr = sPar[0][nl], di = sPar[1][nl];
            float gr = sigm(acc[0][tm][tn][2 * j + c] + sPar[2][nl]);
            float gi = sigm(acc[1][tm][tn][2 * j + c] + sPar[3][nl]);

            float inv = 1.f / (dr * dr + di * di);
            float numr = hra[c] + eta * (zra[c] - vra[c]);
            float numi = hia[c] + eta * (zia[c] - via[c]);
            float xr = (numr * dr + numi * di) * inv;
            float xi = (numi * dr - numr * di) * inv;
            float ur = xr + vra[c], ui = xi + via[c];
            float znr = gr * ur - gi * ui + (1.f - gr) * zra[c] + gi * zia[c];
            float zni = gr * ui + gi * ur + (1.f - gr) * zia[c] - gi * zra[c];
            znv[c] = znr; ziv[c] = zni;
            vnv[c] = vra[c] + xr - znr;
            viv[c] = via[c] + xi - zni;
            if (last) {
                float amp = sqrtf(znr * znr + zni * zni);
                ov[c] = znr * sigm(alv * (amp - thv));   // Re(z*mask)
            }
        }
        *(float2*)(zro + off) = make_float2(znv[0], znv[1]);
        *(float2*)(zio + off) = make_float2(ziv[0], ziv[1]);
        *(float2*)(vro + off) = make_float2(vnv[0], vnv[1]);
        *(float2*)(vio + off) = make_float2(viv[0], viv[1]);
        if (last && (long long)off + 2 <= outCap) {
            *(float2*)(out + off) = make_float2(ov[0], ov[1]);
        }
    }
}

// ---------------- host launcher ----------------
extern "C" void kernel_launch(void* const* d_in, const int* in_sizes, int n_in,
                              void* d_out, int out_size) {
    const void* pA[2] = {0, 0}; int nA = 0;
    const void* pY[2] = {0, 0}; int nY = 0;
    const void* pW[4] = {0, 0, 0, 0}; int nW = 0;
    const void* pB[6] = {0, 0, 0, 0, 0, 0}; int nB = 0;
    const void* pS[2] = {0, 0}; int nS = 0;
    const void* pEta  = 0;

    for (int i = 0; i < n_in; ++i) {
        const void* p = d_in[i];
        long long s = in_sizes[i];
        if      (s == (long long)B_ * M_ * N_) { if (nA < 2) pA[nA++] = p; }
        else if (s == (long long)B_ * M_)      { if (nY < 2) pY[nY++] = p; }
        else if (s == (long long)L_ * N_ * N_) { if (nW < 4) pW[nW++] = p; }
        else if (s == (long long)L_ * N_)      { if (nB < 6) pB[nB++] = p; }
        else if (s == (long long)L_)           { pEta = p; }
        else if (s == 1)                       { if (nS < 2) pS[nS++] = p; }
    }
    if (!(nA == 2 && nY == 2 && nW == 4 && nB == 6 && nS == 2 && pEta)) return;

    long long outCap = (long long)out_size;
    if (outCap > (long long)NB) outCap = (long long)NB;

    const int smemBytes = (2 * 128 * 36 + 2 * 64 * 36) * 4;   // 55296
    cudaFuncSetAttribute(k_layer, cudaFuncAttributeMaxDynamicSharedMemorySize, smemBytes);

    k_init<<<1, 256>>>(pA[0]);
    k_prep<<<(4 * L_ * N_ * N_) / 256, 256>>>(pW[0], pW[1], pW[2], pW[3]);
    k_ahy<<<B_ / 4, 256>>>(pY[0], pY[1], pA[0], pA[1]);
    k_layer0<<<(B_ * N_) / 256, 256>>>(pB[0], pB[1], pEta, pB[2], pB[3], pB[4], pB[5]);
    for (int l = 1; l < L_; ++l) {
        k_layer<<<dim3(N_ / 64, B_ / 128), 256, smemBytes>>>(
            pB[2], pB[3], pB[4], pB[5],
            pB[0], pB[1], pEta,
            l, (l + 1) & 1, l & 1, (l == L_ - 1) ? 1 : 0,
            pS[0], pS[1], (float*)d_out, outCap);
    }
}

// round 14
// speedup vs baseline: 1.3408x; 1.3408x over previous
#include <cuda_runtime.h>
#include <cuda_bf16.h>
#include <cstdint>
#include <math.h>

#define B_ 16384
#define N_ 256
#define M_ 64
#define L_ 10
#define NB (B_ * N_)

// Planes: 0 Ahy_r, 1 Ahy_i, 2+s zr[s], 4+s zi[s], 6+s vr[s], 8+s vi[s]
__device__ float g_scr[10u * (unsigned)NB];
__device__ float g_wts[4 * L_ * N_ * N_];   // f32 weights: [l][s][n][k], s: Wr,Ur,Wi,Ui
__device__ float g_stat[4 * N_];
__device__ int   g_bf16;

__device__ __forceinline__ float sigm(float x) { return 1.f / (1.f + __expf(-x)); }
__device__ __forceinline__ float* plane(int p) { return g_scr + (unsigned)p * (unsigned)NB; }
__device__ __forceinline__ float lda(const void* p, unsigned idx, int isbf) {
    if (isbf) return __bfloat162float(((const __nv_bfloat16*)p)[idx]);
    return ((const float*)p)[idx];
}
__device__ __forceinline__ void mma8(float* c, const float* a, const float* b) {
    asm volatile(
        "mma.sync.aligned.m16n8k8.row.col.f32.tf32.tf32.f32 "
        "{%0,%1,%2,%3}, {%4,%5,%6,%7}, {%8,%9}, {%0,%1,%2,%3};\n"
        : "+f"(c[0]), "+f"(c[1]), "+f"(c[2]), "+f"(c[3])
        : "r"(__float_as_uint(a[0])), "r"(__float_as_uint(a[1])),
          "r"(__float_as_uint(a[2])), "r"(__float_as_uint(a[3])),
          "r"(__float_as_uint(b[0])), "r"(__float_as_uint(b[1])));
}

// ---------------- K_init: probe dtype + zero stats (1 block) ----------------
__global__ void k_init(const void* A) {
    __shared__ int sane;
    unsigned t = threadIdx.x;
    if (t == 0) sane = 0;
#pragma unroll
    for (int j = 0; j < 4; j++) g_stat[t + 256u * j] = 0.f;
    __syncthreads();
    const unsigned short* h = (const unsigned short*)A;
    int loc = 0;
#pragma unroll
    for (int j = 0; j < 8; j++) {
        unsigned short v = h[2 * (t * 8 + j)];
        unsigned e = (v >> 7) & 0xFF;
        if (v == 0 || (e >= 100 && e <= 140)) loc++;
    }
    atomicAdd(&sane, loc);
    __syncthreads();
    if (t == 0) g_bf16 = (sane > 1228) ? 1 : 0;
}

// ---------------- K_prep: weights -> f32 arena [l][s][n][k] ----------------
__global__ void k_prep(const void* w0, const void* w1, const void* w2, const void* w3) {
    const int isbf = g_bf16;
    unsigned idx = blockIdx.x * 256u + threadIdx.x;
    unsigned s = (idx >> 16) & 3u;
    unsigned l = idx >> 18;
    unsigned nk = idx & 65535u;
    const void* ws = (s == 0) ? w0 : (s == 1) ? w1 : (s == 2) ? w2 : w3;
    g_wts[((l * 4u + s) << 16) + nk] = lda(ws, (l << 16) + nk, isbf);
}

// ---------------- K1: A^H y + BN partial stats (float4) ----------------
__global__ void k_ahy(const void* yrv, const void* yiv, const void* Arv, const void* Aiv) {
    __shared__ float syr[4][64], syi[4][64];
    const unsigned t = threadIdx.x, tx = t & 63u, ty = t >> 6;
    const unsigned b0 = blockIdx.x * 4u;
    const int isbf = g_bf16;
    {
        unsigned r = t >> 6, c = t & 63u;
        syr[r][c] = lda(yrv, (b0 + r) * 64u + c, isbf);
        syi[r][c] = lda(yiv, (b0 + r) * 64u + c, isbf);
    }
    __syncthreads();

    float4 ar = make_float4(0.f, 0.f, 0.f, 0.f);
    float4 ai = make_float4(0.f, 0.f, 0.f, 0.f);
    if (!isbf) {
        const float4* A4r = (const float4*)Arv;
        const float4* A4i = (const float4*)Aiv;
        size_t base = (size_t)(b0 + ty) * 4096u + tx;
#pragma unroll 8
        for (int m = 0; m < 64; m++) {
            float4 pr = A4r[base + (size_t)m * 64u];
            float4 pi = A4i[base + (size_t)m * 64u];
            float wr = syr[ty][m], wi = syi[ty][m];
            ar.x += pr.x * wr + pi.x * wi;  ai.x += pr.x * wi - pi.x * wr;
            ar.y += pr.y * wr + pi.y * wi;  ai.y += pr.y * wi - pi.y * wr;
            ar.z += pr.z * wr + pi.z * wi;  ai.z += pr.z * wi - pi.z * wr;
            ar.w += pr.w * wr + pi.w * wi;  ai.w += pr.w * wi - pi.w * wr;
        }
    } else {
        size_t base = (size_t)(b0 + ty) * 16384u + tx * 4u;
        const __nv_bfloat16* Abr = (const __nv_bfloat16*)Arv;
        const __nv_bfloat16* Abi = (const __nv_bfloat16*)Aiv;
#pragma unroll 4
        for (int m = 0; m < 64; m++) {
            float wr = syr[ty][m], wi = syi[ty][m];
            size_t o = base + (size_t)m * 256u;
            float p0r = __bfloat162float(Abr[o]),     p0i = __bfloat162float(Abi[o]);
            float p1r = __bfloat162float(Abr[o + 1]), p1i = __bfloat162float(Abi[o + 1]);
            float p2r = __bfloat162float(Abr[o + 2]), p2i = __bfloat162float(Abi[o + 2]);
            float p3r = __bfloat162float(Abr[o + 3]), p3i = __bfloat162float(Abi[o + 3]);
            ar.x += p0r * wr + p0i * wi;  ai.x += p0r * wi - p0i * wr;
            ar.y += p1r * wr + p1i * wi;  ai.y += p1r * wi - p1i * wr;
            ar.z += p2r * wr + p2i * wi;  ai.z += p2r * wi - p2i * wr;
            ar.w += p3r * wr + p3i * wi;  ai.w += p3r * wi - p3i * wr;
        }
    }
    unsigned o4 = (b0 + ty) * 64u + tx;
    ((float4*)plane(0))[o4] = ar;
    ((float4*)plane(1))[o4] = ai;

    unsigned n0 = tx * 4u;
    atomicAdd(&g_stat[n0],        ar.x); atomicAdd(&g_stat[256u + n0],        ar.x * ar.x);
    atomicAdd(&g_stat[n0 + 1],    ar.y); atomicAdd(&g_stat[256u + n0 + 1],    ar.y * ar.y);
    atomicAdd(&g_stat[n0 + 2],    ar.z); atomicAdd(&g_stat[256u + n0 + 2],    ar.z * ar.z);
    atomicAdd(&g_stat[n0 + 3],    ar.w); atomicAdd(&g_stat[256u + n0 + 3],    ar.w * ar.w);
    atomicAdd(&g_stat[512u + n0],     ai.x); atomicAdd(&g_stat[768u + n0],     ai.x * ai.x);
    atomicAdd(&g_stat[512u + n0 + 1], ai.y); atomicAdd(&g_stat[768u + n0 + 1], ai.y * ai.y);
    atomicAdd(&g_stat[512u + n0 + 2], ai.z); atomicAdd(&g_stat[768u + n0 + 2], ai.z * ai.z);
    atomicAdd(&g_stat[512u + n0 + 3], ai.w); atomicAdd(&g_stat[768u + n0 + 3], ai.w * ai.w);
}

// ---------------- K3: BN finalize + layer 0 ----------------
__global__ void k_layer0(const void* wdr, const void* wdi, const void* reta,
                         const void* br, const void* ubr,
                         const void* bi, const void* ubi) {
    const int isbf = g_bf16;
    unsigned idx = blockIdx.x * 256u + threadIdx.x;
    unsigned n = idx & (unsigned)(N_ - 1);
    const float invB = 1.f / (float)B_;
    float mr = g_stat[n] * invB;
    float istr = rsqrtf(g_stat[256u + n] * invB - mr * mr + 1e-5f);
    float mi = g_stat[512u + n] * invB;
    float isti = rsqrtf(g_stat[768u + n] * invB - mi * mi + 1e-5f);

    float* Ahr = plane(0); float* Ahi = plane(1);
    float eta = log1pf(expf(lda(reta, 0, isbf)));
    float arr = (Ahr[idx] - mr) * istr;
    float aii = (Ahi[idx] - mi) * isti;
    Ahr[idx] = arr;
    Ahi[idx] = aii;
    float dr = lda(wdr, n, isbf) + eta, di = lda(wdi, n, isbf);
    float inv = 1.f / (dr * dr + di * di);
    float xr = (arr * dr + aii * di) * inv;
    float xi = (aii * dr - arr * di) * inv;
    float gr = sigm(lda(br, n, isbf) + lda(ubr, n, isbf));
    float gi = sigm(lda(bi, n, isbf) + lda(ubi, n, isbf));
    float zr = gr * xr - gi * xi;
    float zi = gr * xi + gi * xr;
    plane(2)[idx] = zr;
    plane(4)[idx] = zi;
    plane(6)[idx] = xr - zr;
    plane(8)[idx] = xi - zi;
}

// ---------------- K4: fused layer — reg-staged tf32 MMA + complex epilogue ----
// grid (4,128), 256 thr; tile 128x64; 32 chunks (4 operand pairs x 8 kc).
__global__ __launch_bounds__(256, 2) void k_layer(
    const void* br, const void* ubr, const void* bi, const void* ubi,
    const void* wdr, const void* wdi, const void* reta,
    int loff, int si, int so, int last,
    const void* thrp, const void* alphap,
    float* __restrict__ out, long long outCap)
{
    __shared__ float sA[128][36];
    __shared__ float sB[64][36];
    __shared__ float sPar[4][64];

    const int isbf = g_bf16;
    const unsigned tid  = threadIdx.x;
    const unsigned lane = tid & 31u, warp = tid >> 5;
    const unsigned wrow = (warp >> 1) * 32u;
    const unsigned wcol = (warp & 1u) * 32u;
    const unsigned tg = lane >> 2, tc = lane & 3u;
    const unsigned rowBase = blockIdx.y * 128u;
    const unsigned colBase = blockIdx.x * 64u;
    const unsigned siu = (unsigned)(si & 1);

    float eta = log1pf(expf(lda(reta, (unsigned)loff, isbf)));
    if (tid < 64u) {
        unsigned bn = (unsigned)loff * 256u + colBase + tid;
        sPar[0][tid] = lda(wdr, bn, isbf) + eta;
        sPar[1][tid] = lda(wdi, bn, isbf);
        sPar[2][tid] = lda(br, bn, isbf) + lda(ubr, bn, isbf);
        sPar[3][tid] = lda(bi, bn, isbf) + lda(ubi, bn, isbf);
    }

    float acc[2][2][4][4];
#pragma unroll
    for (int a = 0; a < 2; a++)
#pragma unroll
        for (int b = 0; b < 2; b++)
#pragma unroll
            for (int c = 0; c < 4; c++)
#pragma unroll
                for (int d = 0; d < 4; d++) acc[a][b][c][d] = 0.f;

    // s-order: zr, vr, zi, vi ; comp = s>>1
    const float* __restrict__ zri = plane(2 + (int)siu);
    const float* __restrict__ zii = plane(4 + (int)siu);
    const float* __restrict__ vri = plane(6 + (int)siu);
    const float* __restrict__ vii = plane(8 + (int)siu);
    const float* Asrc[4] = { zri, vri, zii, vii };

    const unsigned rA = tid >> 3;            // 0..31 (A rows: +32*i, B rows: +32*i, i<2)
    const unsigned c4 = (tid & 7u) * 4u;     // 0,4,...,28
    uint4 stA[4], stB[2];

#define LOADREGS(Ap_, Wp_, kc_) do {                                               \
        _Pragma("unroll")                                                          \
        for (int i_ = 0; i_ < 4; i_++)                                             \
            stA[i_] = *(const uint4*)((Ap_) + (rowBase + rA + i_ * 32u) * 256u + (kc_) + c4); \
        _Pragma("unroll")                                                          \
        for (int i_ = 0; i_ < 2; i_++)                                             \
            stB[i_] = *(const uint4*)((Wp_) + (colBase + rA + i_ * 32u) * 256u + (kc_) + c4); \
    } while (0)

#define STOREREGS() do {                                                           \
        _Pragma("unroll")                                                          \
        for (int i_ = 0; i_ < 4; i_++)                                             \
            *(uint4*)(&sA[rA + i_ * 32u][c4]) = stA[i_];                           \
        _Pragma("unroll")                                                          \
        for (int i_ = 0; i_ < 2; i_++)                                             \
            *(uint4*)(&sB[rA + i_ * 32u][c4]) = stB[i_];                           \
    } while (0)

    {
        const float* Wp0 = g_wts + (((unsigned)loff * 4u + 0u) << 16);
        LOADREGS(Asrc[0], Wp0, 0u);
    }

#pragma unroll
    for (int s = 0; s < 4; ++s) {
        const float* Ap  = Asrc[s];
        const float* Wp  = g_wts + (((unsigned)loff * 4u + (unsigned)s) << 16);
        const float* ApN = Asrc[(s < 3) ? s + 1 : 3];
        const float* WpN = g_wts + (((unsigned)loff * 4u + (unsigned)((s < 3) ? s + 1 : 3)) << 16);
        const int comp = s >> 1;
        for (int k8 = 0; k8 < 8; ++k8) {
            __syncthreads();                 // previous chunk's MMAs done
            STOREREGS();
            __syncthreads();                 // chunk visible
            if (k8 < 7)      LOADREGS(Ap,  Wp,  (unsigned)(k8 + 1) * 32u);
            else if (s < 3)  LOADREGS(ApN, WpN, 0u);
            // MMA over this 32-K chunk (latency of the LDGs above hidden here)
#pragma unroll
            for (unsigned kk = 0; kk < 32u; kk += 8u) {
                float af[2][4];
#pragma unroll
                for (int tm = 0; tm < 2; tm++) {
                    unsigned r0 = wrow + tm * 16u + tg;
                    af[tm][0] = sA[r0][kk + tc];
                    af[tm][1] = sA[r0 + 8u][kk + tc];
                    af[tm][2] = sA[r0][kk + tc + 4u];
                    af[tm][3] = sA[r0 + 8u][kk + tc + 4u];
                }
                float bfv[4][2];
#pragma unroll
                for (int tn = 0; tn < 4; tn++) {
                    unsigned n0 = wcol + tn * 8u + tg;
                    bfv[tn][0] = sB[n0][kk + tc];
                    bfv[tn][1] = sB[n0][kk + tc + 4u];
                }
#pragma unroll
                for (int tm = 0; tm < 2; tm++)
#pragma unroll
                    for (int tn = 0; tn < 4; tn++)
                        mma8(acc[comp][tm][tn], af[tm], bfv[tn]);
            }
        }
    }
#undef LOADREGS
#undef STOREREGS

    // ----- epilogue (float2) -----
    float thv = 0.f, alv = 0.f;
    if (last) { thv = lda(thrp, 0, isbf); alv = lda(alphap, 0, isbf); }

    const float* __restrict__ Ahr = plane(0);
    const float* __restrict__ Ahi = plane(1);
    float* __restrict__ zro = plane(2 + (so & 1));
    float* __restrict__ zio = plane(4 + (so & 1));
    float* __restrict__ vro = plane(6 + (so & 1));
    float* __restrict__ vio = plane(8 + (so & 1));

#pragma unroll
    for (int tm = 0; tm < 2; tm++)
#pragma unroll
    for (int j = 0; j < 2; j++)
#pragma unroll
    for (int tn = 0; tn < 4; tn++) {
        unsigned b = rowBase + wrow + tm * 16u + j * 8u + tg;
        unsigned ln = wcol + tn * 8u + 2u * tc;
        unsigned off = b * (unsigned)N_ + colBase + ln;

        float2 z2 = *(const float2*)(zri + off);
        float2 i2 = *(const float2*)(zii + off);
        float2 v2 = *(const float2*)(vri + off);
        float2 w2 = *(const float2*)(vii + off);
        float2 h2 = *(const float2*)(Ahr + off);
        float2 g2 = *(const float2*)(Ahi + off);

        float zra[2] = {z2.x, z2.y}, zia[2] = {i2.x, i2.y};
        float vra[2] = {v2.x, v2.y}, via[2] = {w2.x, w2.y};
        float hra[2] = {h2.x, h2.y}, hia[2] = {g2.x, g2.y};

        float znv[2], ziv[2], vnv[2], viv[2], ov[2];
#pragma unroll
        for (int c = 0; c < 2; c++) {
            unsigned nl = ln + c;
            float dr = sPar[0][nl], di = sPar[1][nl];
            float gr = sigm(acc[0][tm][tn][2 * j + c] + sPar[2][nl]);
            float gi = sigm(acc[1][tm][tn][2 * j + c] + sPar[3][nl]);

            float inv = 1.f / (dr * dr + di * di);
            float numr = hra[c] + eta * (zra[c] - vra[c]);
            float numi = hia[c] + eta * (zia[c] - via[c]);
            float xr = (numr * dr + numi * di) * inv;
            float xi = (numi * dr - numr * di) * inv;
            float ur = xr + vra[c], ui = xi + via[c];
            float znr = gr * ur - gi * ui + (1.f - gr) * zra[c] + gi * zia[c];
            float zni = gr * ui + gi * ur + (1.f - gr) * zia[c] - gi * zra[c];
            znv[c] = znr; ziv[c] = zni;
            vnv[c] = vra[c] + xr - znr;
            viv[c] = via[c] + xi - zni;
            if (last) {
                float amp = sqrtf(znr * znr + zni * zni);
                ov[c] = znr * sigm(alv * (amp - thv));   // Re(z*mask)
            }
        }
        *(float2*)(zro + off) = make_float2(znv[0], znv[1]);
        *(float2*)(zio + off) = make_float2(ziv[0], ziv[1]);
        *(float2*)(vro + off) = make_float2(vnv[0], vnv[1]);
        *(float2*)(vio + off) = make_float2(viv[0], viv[1]);
        if (last && (long long)off + 2 <= outCap) {
            *(float2*)(out + off) = make_float2(ov[0], ov[1]);
        }
    }
}

// ---------------- host launcher ----------------
extern "C" void kernel_launch(void* const* d_in, const int* in_sizes, int n_in,
                              void* d_out, int out_size) {
    const void* pA[2] = {0, 0}; int nA = 0;
    const void* pY[2] = {0, 0}; int nY = 0;
    const void* pW[4] = {0, 0, 0, 0}; int nW = 0;
    const void* pB[6] = {0, 0, 0, 0, 0, 0}; int nB = 0;
    const void* pS[2] = {0, 0}; int nS = 0;
    const void* pEta  = 0;

    for (int i = 0; i < n_in; ++i) {
        const void* p = d_in[i];
        long long s = in_sizes[i];
        if      (s == (long long)B_ * M_ * N_) { if (nA < 2) pA[nA++] = p; }
        else if (s == (long long)B_ * M_)      { if (nY < 2) pY[nY++] = p; }
        else if (s == (long long)L_ * N_ * N_) { if (nW < 4) pW[nW++] = p; }
        else if (s == (long long)L_ * N_)      { if (nB < 6) pB[nB++] = p; }
        else if (s == (long long)L_)           { pEta = p; }
        else if (s == 1)                       { if (nS < 2) pS[nS++] = p; }
    }
    if (!(nA == 2 && nY == 2 && nW == 4 && nB == 6 && nS == 2 && pEta)) return;

    long long outCap = (long long)out_size;
    if (outCap > (long long)NB) outCap = (long long)NB;

    k_init<<<1, 256>>>(pA[0]);
    k_prep<<<(4 * L_ * N_ * N_) / 256, 256>>>(pW[0], pW[1], pW[2], pW[3]);
    k_ahy<<<B_ / 4, 256>>>(pY[0], pY[1], pA[0], pA[1]);
    k_layer0<<<(B_ * N_) / 256, 256>>>(pB[0], pB[1], pEta, pB[2], pB[3], pB[4], pB[5]);
    for (int l = 1; l < L_; ++l) {
        k_layer<<<dim3(N_ / 64, B_ / 128), 256>>>(
            pB[2], pB[3], pB[4], pB[5],
            pB[0], pB[1], pEta,
            l, (l + 1) & 1, l & 1, (l == L_ - 1) ? 1 : 0,
            pS[0], pS[1], (float*)d_out, outCap);
    }
}

// round 15
// speedup vs baseline: 1.3516x; 1.0081x over previous
#include <cuda_runtime.h>
#include <cuda_bf16.h>
#include <cstdint>
#include <math.h>

#define B_ 16384
#define N_ 256
#define M_ 64
#define L_ 10
#define NB (B_ * N_)

// Planes: 0 Ahy_r, 1 Ahy_i, 2+s zr[s], 4+s zi[s], 6+s vr[s], 8+s vi[s]
__device__ float g_scr[10u * (unsigned)NB];
__device__ float g_wts[4 * L_ * N_ * N_];   // f32 weights: [l][s][n][k], s: Wr,Ur,Wi,Ui
__device__ float g_stat[4 * N_];
__device__ int   g_bf16;

__device__ __forceinline__ float sigm(float x) { return 1.f / (1.f + __expf(-x)); }
__device__ __forceinline__ float* plane(int p) { return g_scr + (unsigned)p * (unsigned)NB; }
__device__ __forceinline__ float lda(const void* p, unsigned idx, int isbf) {
    if (isbf) return __bfloat162float(((const __nv_bfloat16*)p)[idx]);
    return ((const float*)p)[idx];
}
__device__ __forceinline__ void mma8(float* c, const float* a, const float* b) {
    asm volatile(
        "mma.sync.aligned.m16n8k8.row.col.f32.tf32.tf32.f32 "
        "{%0,%1,%2,%3}, {%4,%5,%6,%7}, {%8,%9}, {%0,%1,%2,%3};\n"
        : "+f"(c[0]), "+f"(c[1]), "+f"(c[2]), "+f"(c[3])
        : "r"(__float_as_uint(a[0])), "r"(__float_as_uint(a[1])),
          "r"(__float_as_uint(a[2])), "r"(__float_as_uint(a[3])),
          "r"(__float_as_uint(b[0])), "r"(__float_as_uint(b[1])));
}

// ---- K_prep (launch 1): per-block dtype probe + weight convert + stat zero ----
__global__ void k_prep(const void* A, const void* w0, const void* w1,
                       const void* w2, const void* w3) {
    __shared__ int sane;
    unsigned t = threadIdx.x;
    if (t == 0) sane = 0;
    __syncthreads();
    const unsigned short* h = (const unsigned short*)A;
    int loc = 0;
#pragma unroll
    for (int j = 0; j < 8; j++) {
        unsigned short v = h[2 * (t * 8 + j)];
        unsigned e = (v >> 7) & 0xFF;
        if (v == 0 || (e >= 100 && e <= 140)) loc++;
    }
    atomicAdd(&sane, loc);
    __syncthreads();
    const int isbf = (sane > 1228) ? 1 : 0;

    if (blockIdx.x == 0) {
        if (t == 0) g_bf16 = isbf;          // for later kernels (stream-ordered)
#pragma unroll
        for (int j = 0; j < 4; j++) g_stat[t + 256u * j] = 0.f;
    }

    unsigned idx = blockIdx.x * 256u + t;    // 0 .. 4*L*N*N-1
    unsigned s = (idx >> 16) & 3u;
    unsigned l = idx >> 18;
    unsigned nk = idx & 65535u;
    const void* ws = (s == 0) ? w0 : (s == 1) ? w1 : (s == 2) ? w2 : w3;
    g_wts[((l * 4u + s) << 16) + nk] = lda(ws, (l << 16) + nk, isbf);
}

// ---------------- K1 (launch 2): A^H y + BN partial stats (float4) ----------------
__global__ void k_ahy(const void* yrv, const void* yiv, const void* Arv, const void* Aiv) {
    __shared__ float syr[4][64], syi[4][64];
    const unsigned t = threadIdx.x, tx = t & 63u, ty = t >> 6;
    const unsigned b0 = blockIdx.x * 4u;
    const int isbf = g_bf16;
    {
        unsigned r = t >> 6, c = t & 63u;
        syr[r][c] = lda(yrv, (b0 + r) * 64u + c, isbf);
        syi[r][c] = lda(yiv, (b0 + r) * 64u + c, isbf);
    }
    __syncthreads();

    float4 ar = make_float4(0.f, 0.f, 0.f, 0.f);
    float4 ai = make_float4(0.f, 0.f, 0.f, 0.f);
    if (!isbf) {
        const float4* A4r = (const float4*)Arv;
        const float4* A4i = (const float4*)Aiv;
        size_t base = (size_t)(b0 + ty) * 4096u + tx;
#pragma unroll 8
        for (int m = 0; m < 64; m++) {
            float4 pr = A4r[base + (size_t)m * 64u];
            float4 pi = A4i[base + (size_t)m * 64u];
            float wr = syr[ty][m], wi = syi[ty][m];
            ar.x += pr.x * wr + pi.x * wi;  ai.x += pr.x * wi - pi.x * wr;
            ar.y += pr.y * wr + pi.y * wi;  ai.y += pr.y * wi - pi.y * wr;
            ar.z += pr.z * wr + pi.z * wi;  ai.z += pr.z * wi - pi.z * wr;
            ar.w += pr.w * wr + pi.w * wi;  ai.w += pr.w * wi - pi.w * wr;
        }
    } else {
        size_t base = (size_t)(b0 + ty) * 16384u + tx * 4u;
        const __nv_bfloat16* Abr = (const __nv_bfloat16*)Arv;
        const __nv_bfloat16* Abi = (const __nv_bfloat16*)Aiv;
#pragma unroll 4
        for (int m = 0; m < 64; m++) {
            float wr = syr[ty][m], wi = syi[ty][m];
            size_t o = base + (size_t)m * 256u;
            float p0r = __bfloat162float(Abr[o]),     p0i = __bfloat162float(Abi[o]);
            float p1r = __bfloat162float(Abr[o + 1]), p1i = __bfloat162float(Abi[o + 1]);
            float p2r = __bfloat162float(Abr[o + 2]), p2i = __bfloat162float(Abi[o + 2]);
            float p3r = __bfloat162float(Abr[o + 3]), p3i = __bfloat162float(Abi[o + 3]);
            ar.x += p0r * wr + p0i * wi;  ai.x += p0r * wi - p0i * wr;
            ar.y += p1r * wr + p1i * wi;  ai.y += p1r * wi - p1i * wr;
            ar.z += p2r * wr + p2i * wi;  ai.z += p2r * wi - p2i * wr;
            ar.w += p3r * wr + p3i * wi;  ai.w += p3r * wi - p3i * wr;
        }
    }
    unsigned o4 = (b0 + ty) * 64u + tx;
    ((float4*)plane(0))[o4] = ar;
    ((float4*)plane(1))[o4] = ai;

    unsigned n0 = tx * 4u;
    atomicAdd(&g_stat[n0],        ar.x); atomicAdd(&g_stat[256u + n0],        ar.x * ar.x);
    atomicAdd(&g_stat[n0 + 1],    ar.y); atomicAdd(&g_stat[256u + n0 + 1],    ar.y * ar.y);
    atomicAdd(&g_stat[n0 + 2],    ar.z); atomicAdd(&g_stat[256u + n0 + 2],    ar.z * ar.z);
    atomicAdd(&g_stat[n0 + 3],    ar.w); atomicAdd(&g_stat[256u + n0 + 3],    ar.w * ar.w);
    atomicAdd(&g_stat[512u + n0],     ai.x); atomicAdd(&g_stat[768u + n0],     ai.x * ai.x);
    atomicAdd(&g_stat[512u + n0 + 1], ai.y); atomicAdd(&g_stat[768u + n0 + 1], ai.y * ai.y);
    atomicAdd(&g_stat[512u + n0 + 2], ai.z); atomicAdd(&g_stat[768u + n0 + 2], ai.z * ai.z);
    atomicAdd(&g_stat[512u + n0 + 3], ai.w); atomicAdd(&g_stat[768u + n0 + 3], ai.w * ai.w);
}

// ---------------- K3 (launch 3): BN finalize + layer 0 ----------------
__global__ void k_layer0(const void* wdr, const void* wdi, const void* reta,
                         const void* br, const void* ubr,
                         const void* bi, const void* ubi) {
    const int isbf = g_bf16;
    unsigned idx = blockIdx.x * 256u + threadIdx.x;
    unsigned n = idx & (unsigned)(N_ - 1);
    const float invB = 1.f / (float)B_;
    float mr = g_stat[n] * invB;
    float istr = rsqrtf(g_stat[256u + n] * invB - mr * mr + 1e-5f);
    float mi = g_stat[512u + n] * invB;
    float isti = rsqrtf(g_stat[768u + n] * invB - mi * mi + 1e-5f);

    float* Ahr = plane(0); float* Ahi = plane(1);
    float eta = log1pf(expf(lda(reta, 0, isbf)));
    float arr = (Ahr[idx] - mr) * istr;
    float aii = (Ahi[idx] - mi) * isti;
    Ahr[idx] = arr;
    Ahi[idx] = aii;
    float dr = lda(wdr, n, isbf) + eta, di = lda(wdi, n, isbf);
    float inv = 1.f / (dr * dr + di * di);
    float xr = (arr * dr + aii * di) * inv;
    float xi = (aii * dr - arr * di) * inv;
    float gr = sigm(lda(br, n, isbf) + lda(ubr, n, isbf));
    float gi = sigm(lda(bi, n, isbf) + lda(ubi, n, isbf));
    float zr = gr * xr - gi * xi;
    float zi = gr * xi + gi * xr;
    plane(2)[idx] = zr;
    plane(4)[idx] = zi;
    plane(6)[idx] = xr - zr;
    plane(8)[idx] = xi - zi;
}

// ---- K4 (launches 4..12): fused layer — double-buffered reg-staged tf32 MMA ----
// grid (4,128), 256 thr; tile 128x64; 32 chunks; ONE barrier per chunk.
__global__ __launch_bounds__(256, 2) void k_layer(
    const void* br, const void* ubr, const void* bi, const void* ubi,
    const void* wdr, const void* wdi, const void* reta,
    int loff, int si, int so, int last,
    const void* thrp, const void* alphap,
    float* __restrict__ out, long long outCap)
{
    extern __shared__ float smd[];
    float* sA0 = smd;                    // 128*36
    float* sA1 = sA0 + 128 * 36;
    float* sB0 = sA1 + 128 * 36;         // 64*36
    float* sB1 = sB0 + 64 * 36;
    __shared__ float sPar[4][64];

    const int isbf = g_bf16;
    const unsigned tid  = threadIdx.x;
    const unsigned lane = tid & 31u, warp = tid >> 5;
    const unsigned wrow = (warp >> 1) * 32u;
    const unsigned wcol = (warp & 1u) * 32u;
    const unsigned tg = lane >> 2, tc = lane & 3u;
    const unsigned rowBase = blockIdx.y * 128u;
    const unsigned colBase = blockIdx.x * 64u;
    const unsigned siu = (unsigned)(si & 1);

    float eta = log1pf(expf(lda(reta, (unsigned)loff, isbf)));
    if (tid < 64u) {
        unsigned bn = (unsigned)loff * 256u + colBase + tid;
        sPar[0][tid] = lda(wdr, bn, isbf) + eta;
        sPar[1][tid] = lda(wdi, bn, isbf);
        sPar[2][tid] = lda(br, bn, isbf) + lda(ubr, bn, isbf);
        sPar[3][tid] = lda(bi, bn, isbf) + lda(ubi, bn, isbf);
    }

    float acc[2][2][4][4];
#pragma unroll
    for (int a = 0; a < 2; a++)
#pragma unroll
        for (int b = 0; b < 2; b++)
#pragma unroll
            for (int c = 0; c < 4; c++)
#pragma unroll
                for (int d = 0; d < 4; d++) acc[a][b][c][d] = 0.f;

    const float* __restrict__ zri = plane(2 + (int)siu);
    const float* __restrict__ zii = plane(4 + (int)siu);
    const float* __restrict__ vri = plane(6 + (int)siu);
    const float* __restrict__ vii = plane(8 + (int)siu);
    const float* Asrc[4] = { zri, vri, zii, vii };   // comp = s>>1

    const unsigned rA = tid >> 3;
    const unsigned c4 = (tid & 7u) * 4u;
    uint4 stA[4], stB[2];

#define LOADREGS(Ap_, Wp_, kc_) do {                                               \
        _Pragma("unroll")                                                          \
        for (int i_ = 0; i_ < 4; i_++)                                             \
            stA[i_] = *(const uint4*)((Ap_) + (rowBase + rA + i_ * 32u) * 256u + (kc_) + c4); \
        _Pragma("unroll")                                                          \
        for (int i_ = 0; i_ < 2; i_++)                                             \
            stB[i_] = *(const uint4*)((Wp_) + (colBase + rA + i_ * 32u) * 256u + (kc_) + c4); \
    } while (0)

#define STOREREGS(dA_, dB_) do {                                                   \
        _Pragma("unroll")                                                          \
        for (int i_ = 0; i_ < 4; i_++)                                             \
            *(uint4*)((dA_) + (rA + i_ * 32u) * 36u + c4) = stA[i_];               \
        _Pragma("unroll")                                                          \
        for (int i_ = 0; i_ < 2; i_++)                                             \
            *(uint4*)((dB_) + (rA + i_ * 32u) * 36u + c4) = stB[i_];               \
    } while (0)

    {
        const float* Wp0 = g_wts + (((unsigned)loff * 4u + 0u) << 16);
        LOADREGS(Asrc[0], Wp0, 0u);
    }

#pragma unroll
    for (int s = 0; s < 4; ++s) {
        const float* Ap  = Asrc[s];
        const float* Wp  = g_wts + (((unsigned)loff * 4u + (unsigned)s) << 16);
        const float* ApN = Asrc[(s < 3) ? s + 1 : 3];
        const float* WpN = g_wts + (((unsigned)loff * 4u + (unsigned)((s < 3) ? s + 1 : 3)) << 16);
        const int comp = s >> 1;
        for (int k8 = 0; k8 < 8; ++k8) {
            float* dA = (k8 & 1) ? sA1 : sA0;   // chunk parity = k8&1 (s*8 even)
            float* dB = (k8 & 1) ? sB1 : sB0;
            STOREREGS(dA, dB);
            __syncthreads();                    // single barrier per chunk
            if (k8 < 7)      LOADREGS(Ap,  Wp,  (unsigned)(k8 + 1) * 32u);
            else if (s < 3)  LOADREGS(ApN, WpN, 0u);
#pragma unroll
            for (unsigned kk = 0; kk < 32u; kk += 8u) {
                float af[2][4];
#pragma unroll
                for (int tm = 0; tm < 2; tm++) {
                    unsigned r0 = wrow + tm * 16u + tg;
                    af[tm][0] = dA[r0 * 36u + kk + tc];
                    af[tm][1] = dA[(r0 + 8u) * 36u + kk + tc];
                    af[tm][2] = dA[r0 * 36u + kk + tc + 4u];
                    af[tm][3] = dA[(r0 + 8u) * 36u + kk + tc + 4u];
                }
                float bfv[4][2];
#pragma unroll
                for (int tn = 0; tn < 4; tn++) {
                    unsigned n0 = wcol + tn * 8u + tg;
                    bfv[tn][0] = dB[n0 * 36u + kk + tc];
                    bfv[tn][1] = dB[n0 * 36u + kk + tc + 4u];
                }
#pragma unroll
                for (int tm = 0; tm < 2; tm++)
#pragma unroll
                    for (int tn = 0; tn < 4; tn++)
                        mma8(acc[comp][tm][tn], af[tm], bfv[tn]);
            }
        }
    }
#undef LOADREGS
#undef STOREREGS

    // ----- epilogue (float2) -----
    float thv = 0.f, alv = 0.f;
    if (last) { thv = lda(thrp, 0, isbf); alv = lda(alphap, 0, isbf); }

    const float* __restrict__ Ahr = plane(0);
    const float* __restrict__ Ahi = plane(1);
    float* __restrict__ zro = plane(2 + (so & 1));
    float* __restrict__ zio = plane(4 + (so & 1));
    float* __restrict__ vro = plane(6 + (so & 1));
    float* __restrict__ vio = plane(8 + (so & 1));

#pragma unroll
    for (int tm = 0; tm < 2; tm++)
#pragma unroll
    for (int j = 0; j < 2; j++)
#pragma unroll
    for (int tn = 0; tn < 4; tn++) {
        unsigned b = rowBase + wrow + tm * 16u + j * 8u + tg;
        unsigned ln = wcol + tn * 8u + 2u * tc;
        unsigned off = b * (unsigned)N_ + colBase + ln;

        float2 z2 = *(const float2*)(zri + off);
        float2 i2 = *(const float2*)(zii + off);
        float2 v2 = *(const float2*)(vri + off);
        float2 w2 = *(const float2*)(vii + off);
        float2 h2 = *(const float2*)(Ahr + off);
        float2 g2 = *(const float2*)(Ahi + off);

        float zra[2] = {z2.x, z2.y}, zia[2] = {i2.x, i2.y};
        float vra[2] = {v2.x, v2.y}, via[2] = {w2.x, w2.y};
        float hra[2] = {h2.x, h2.y}, hia[2] = {g2.x, g2.y};

        float znv[2], ziv[2], vnv[2], viv[2], ov[2];
#pragma unroll
        for (int c = 0; c < 2; c++) {
            unsigned nl = ln + c;
            float dr = sPar[0][nl], di = sPar[1][nl];
            float gr = sigm(acc[0][tm][tn][2 * j + c] + sPar[2][nl]);
            float gi = sigm(acc[1][tm][tn][2 * j + c] + sPar[3][nl]);

            float inv = 1.f / (dr * dr + di * di);
            float numr = hra[c] + eta * (zra[c] - vra[c]);
            float numi = hia[c] + eta * (zia[c] - via[c]);
            float xr = (numr * dr + numi * di) * inv;
            float xi = (numi * dr - numr * di) * inv;
            float ur = xr + vra[c], ui = xi + via[c];
            float znr = gr * ur - gi * ui + (1.f - gr) * zra[c] + gi * zia[c];
            float zni = gr * ui + gi * ur + (1.f - gr) * zia[c] - gi * zra[c];
            znv[c] = znr; ziv[c] = zni;
            vnv[c] = vra[c] + xr - znr;
            viv[c] = via[c] + xi - zni;
            if (last) {
                float amp = sqrtf(znr * znr + zni * zni);
                ov[c] = znr * sigm(alv * (amp - thv));   // Re(z*mask)
            }
        }
        *(float2*)(zro + off) = make_float2(znv[0], znv[1]);
        *(float2*)(zio + off) = make_float2(ziv[0], ziv[1]);
        *(float2*)(vro + off) = make_float2(vnv[0], vnv[1]);
        *(float2*)(vio + off) = make_float2(viv[0], viv[1]);
        if (last && (long long)off + 2 <= outCap) {
            *(float2*)(out + off) = make_float2(ov[0], ov[1]);
        }
    }
}

// ---------------- host launcher ----------------
extern "C" void kernel_launch(void* const* d_in, const int* in_sizes, int n_in,
                              void* d_out, int out_size) {
    const void* pA[2] = {0, 0}; int nA = 0;
    const void* pY[2] = {0, 0}; int nY = 0;
    const void* pW[4] = {0, 0, 0, 0}; int nW = 0;
    const void* pB[6] = {0, 0, 0, 0, 0, 0}; int nB = 0;
    const void* pS[2] = {0, 0}; int nS = 0;
    const void* pEta  = 0;

    for (int i = 0; i < n_in; ++i) {
        const void* p = d_in[i];
        long long s = in_sizes[i];
        if      (s == (long long)B_ * M_ * N_) { if (nA < 2) pA[nA++] = p; }
        else if (s == (long long)B_ * M_)      { if (nY < 2) pY[nY++] = p; }
        else if (s == (long long)L_ * N_ * N_) { if (nW < 4) pW[nW++] = p; }
        else if (s == (long long)L_ * N_)      { if (nB < 6) pB[nB++] = p; }
        else if (s == (long long)L_)           { pEta = p; }
        else if (s == 1)                       { if (nS < 2) pS[nS++] = p; }
    }
    if (!(nA == 2 && nY == 2 && nW == 4 && nB == 6 && nS == 2 && pEta)) return;

    long long outCap = (long long)out_size;
    if (outCap > (long long)NB) outCap = (long long)NB;

    const int smemBytes = (2 * 128 * 36 + 2 * 64 * 36) * 4;   // 55296
    static int attrSet = 0;
    if (!attrSet) {
        cudaFuncSetAttribute(k_layer, cudaFuncAttributeMaxDynamicSharedMemorySize, smemBytes);
        attrSet = 1;
    }

    k_prep<<<(4 * L_ * N_ * N_) / 256, 256>>>(pA[0], pW[0], pW[1], pW[2], pW[3]);
    k_ahy<<<B_ / 4, 256>>>(pY[0], pY[1], pA[0], pA[1]);
    k_layer0<<<(B_ * N_) / 256, 256>>>(pB[0], pB[1], pEta, pB[2], pB[3], pB[4], pB[5]);
    for (int l = 1; l < L_; ++l) {
        k_layer<<<dim3(N_ / 64, B_ / 128), 256, smemBytes>>>(
            pB[2], pB[3], pB[4], pB[5],
            pB[0], pB[1], pEta,
            l, (l + 1) & 1, l & 1, (l == L_ - 1) ? 1 : 0,
            pS[0], pS[1], (float*)d_out, outCap);
    }
}